// round 4
// baseline (speedup 1.0000x reference)
#include <cuda_runtime.h>

// Fixed problem shape
#define BB 4
#define CC 19
#define HH 256
#define WW 256
#define HW (HH * WW)
#define CHW (CC * HW)
#define RAD 10
#define TS 32
#define EW (TS + 2 * RAD)   // 52
#define NBLK2 256           // K2 block count (64 tiles x 4 images)

// Scratch (device globals; self-resetting at end of each replay)
__device__ float g_ent[BB * HW];
__device__ float g_kl[BB * HW];
__device__ unsigned char g_fg[BB * HW];
__device__ int g_entmax[BB];        // entropy > 0 -> int atomicMax is order-preserving
__device__ double g_sum_wkl;
__device__ double g_sum_w;
__device__ unsigned int g_done;     // K2 completion counter

// ---------------------------------------------------------------------------
// K1: 1 pixel/thread, max occupancy, perfectly coalesced.
// Single pass, no max-subtract (logits/4 are small; exp safe):
//   Z = sum e^t, S = sum t e^t, T = sum s e^t, Zs = sum e^s
//   ent = logZ - S/Z ;  kl = (S-T)/Z - logZ + logZs
// ---------------------------------------------------------------------------
__global__ void __launch_bounds__(256) k1_channelwise(
    const float* __restrict__ student, const float* __restrict__ teacher)
{
    const int b = blockIdx.y;
    const int p = blockIdx.x * 256 + threadIdx.x;
    const size_t base = (size_t)b * CHW + p;

    float Z = 0.f, S = 0.f, Tt = 0.f, Zs = 0.f;
    float t0, mx = -1e30f;

#pragma unroll
    for (int c = 0; c < CC; c++) {
        float tv = __ldg(teacher + base + (size_t)c * HW) * 0.25f;
        float sv = __ldg(student + base + (size_t)c * HW) * 0.25f;
        float e = __expf(tv);
        Z += e;
        S = fmaf(e, tv, S);
        Tt = fmaf(e, sv, Tt);
        Zs += __expf(sv);
        if (c == 0) t0 = tv;
        else        mx = fmaxf(mx, tv);
    }

    const float lZ = __logf(Z);
    const float ent = lZ - S / Z;
    const float kl = (S - Tt) / Z - lZ + __logf(Zs);

    const int idx = b * HW + p;
    g_ent[idx] = ent;
    g_kl[idx] = kl;
    g_fg[idx] = (mx > t0) ? 1 : 0;   // argmax != 0 (ties -> class 0)

    // per-image entropy max: warp shuffle -> smem -> atomicMax
    float entm = ent;
#pragma unroll
    for (int o = 16; o > 0; o >>= 1)
        entm = fmaxf(entm, __shfl_xor_sync(0xFFFFFFFF, entm, o));
    __shared__ float smax[8];
    if ((threadIdx.x & 31) == 0) smax[threadIdx.x >> 5] = entm;
    __syncthreads();
    if (threadIdx.x == 0) {
        float m = smax[0];
#pragma unroll
        for (int w = 1; w < 8; w++) m = fmaxf(m, smax[w]);
        atomicMax(&g_entmax[b], __float_as_int(m));
    }
}

// ---------------------------------------------------------------------------
// K2: bounded EDT (vertical byte-SIMD + horizontal) + boundary + confidence +
// weighted reduction; the last-finishing block finalizes out[0] and resets
// all global accumulators for the next graph replay.
// ---------------------------------------------------------------------------
__global__ void __launch_bounds__(256) k2_edt_weights(float* __restrict__ out)
{
    const int b  = blockIdx.y;
    const int i0 = (blockIdx.x >> 3) * TS;
    const int j0 = (blockIdx.x & 7) * TS;
    const int tid = threadIdx.x;

    __shared__ unsigned char sfg[EW][56];   // 52x52 fg halo (stride 56, u32-aligned)
    __shared__ unsigned char svv[TS][56];   // vertical min-d^2

    // Load fg halo (OOB -> 0 = background)
    for (int t = tid; t < EW * 56; t += 256) {
        int r = t / 56, c = t - r * 56;
        unsigned char f = 0;
        if (c < EW) {
            int gi = i0 - RAD + r, gj = j0 - RAD + c;
            if (gi >= 0 && gi < HH && gj >= 0 && gj < WW)
                f = g_fg[b * HW + gi * WW + gj];
        }
        sfg[r][c] = f;
    }
    __syncthreads();

    // vertical 21-tap min via byte SIMD: term = 200 - fg*(200-d^2), carry-free
    for (int t = tid; t < TS * 13; t += 256) {
        int r = t / 13, wc = (t - r * 13) * 4;
        unsigned int v4 = 0xC8C8C8C8u;
#pragma unroll
        for (int dr = 0; dr < 21; dr++) {
            unsigned int f4 = *(const unsigned int*)&sfg[r + dr][wc];
            int d = dr - RAD;
            v4 = __vminu4(v4, 0xC8C8C8C8u - f4 * (unsigned int)(200 - d * d));
        }
        *(unsigned int*)&svv[r][wc] = v4;
    }
    __syncthreads();

    const float Hm = __int_as_float(g_entmax[b]);
    const float invHm = 1.0f / (Hm + 1e-8f);
    const int ty  = tid >> 3;
    const int tx0 = (tid & 7) * 4;

    float a_wkl = 0.f, a_w = 0.f;
#pragma unroll
    for (int l = 0; l < 4; l++) {
        const int tx = tx0 + l;
        int d2 = 300;
#pragma unroll
        for (int dj = 0; dj < 21; dj++) {
            int dd = dj - RAD;
            d2 = min(d2, dd * dd + (int)svv[ty][tx + dj]);
        }
        if (d2 <= RAD * RAD) {
            float wd = __expf((float)d2 * (-1.0f / 50.0f));   // 2*sigma^2 = 50
            float bnd = 0.f;
            if (sfg[ty + RAD][tx + RAD]) {
                bool er = sfg[ty + RAD - 1][tx + RAD] && sfg[ty + RAD + 1][tx + RAD]
                       && sfg[ty + RAD][tx + RAD - 1] && sfg[ty + RAD][tx + RAD + 1];
                if (!er) bnd = 1.f;
            }
            const int idx = b * HW + (i0 + ty) * WW + (j0 + tx);
            float conf = 0.1f + 0.9f * (1.f - g_ent[idx] * invHm);
            float w = wd * (1.f + bnd) * conf;
            a_wkl += w * g_kl[idx];
            a_w   += w;
        }
    }

#pragma unroll
    for (int o = 16; o > 0; o >>= 1) {
        a_wkl += __shfl_xor_sync(0xFFFFFFFF, a_wkl, o);
        a_w   += __shfl_xor_sync(0xFFFFFFFF, a_w, o);
    }
    __shared__ float r1[8], r2[8];
    if ((tid & 31) == 0) { r1[tid >> 5] = a_wkl; r2[tid >> 5] = a_w; }
    __syncthreads();

    if (tid == 0) {
        float s1 = 0.f, s2 = 0.f;
#pragma unroll
        for (int w = 0; w < 8; w++) { s1 += r1[w]; s2 += r2[w]; }
        atomicAdd(&g_sum_wkl, (double)s1);
        atomicAdd(&g_sum_w, (double)s2);
        __threadfence();
        unsigned int t = atomicAdd(&g_done, 1u);
        if (t == NBLK2 - 1) {   // last block: finalize + reset for next replay
            double swkl = atomicAdd(&g_sum_wkl, 0.0);
            double sw   = atomicAdd(&g_sum_w, 0.0);
            out[0] = (float)(16.0 * swkl / (sw + 1e-8));
            g_sum_wkl = 0.0;
            g_sum_w = 0.0;
#pragma unroll
            for (int bb = 0; bb < BB; bb++) g_entmax[bb] = 0;
            atomicExch(&g_done, 0u);
        }
    }
}

extern "C" void kernel_launch(void* const* d_in, const int* in_sizes, int n_in,
                              void* d_out, int out_size)
{
    const float* student = (const float*)d_in[0];
    const float* teacher = (const float*)d_in[1];
    float* out = (float*)d_out;

    k1_channelwise<<<dim3(HW / 256, BB), 256>>>(student, teacher);
    k2_edt_weights<<<dim3(64, BB), 256>>>(out);
}

// round 5
// speedup vs baseline: 1.1175x; 1.1175x over previous
#include <cuda_runtime.h>

// Fixed problem shape
#define BB 4
#define CC 19
#define HH 256
#define WW 256
#define HW (HH * WW)
#define CHW (CC * HW)
#define RAD 10
#define TS 32
#define EW (TS + 2 * RAD)   // 52 halo rows
#define NBLK2 256           // K2 block count (64 tiles x 4 images)

// Scratch (device globals; self-resetting at end of each replay)
__device__ float g_ent[BB * HW];
__device__ float g_kl[BB * HW];
__device__ unsigned char g_fg[BB * HW];
__device__ int g_entmax[BB];        // entropy > 0 -> int atomicMax is order-preserving
__device__ double g_sum_wkl;
__device__ double g_sum_w;
__device__ unsigned int g_done;     // K2 completion counter

// ---------------------------------------------------------------------------
// K1: 1 pixel/thread, max occupancy, perfectly coalesced. (unchanged from R4)
// ---------------------------------------------------------------------------
__global__ void __launch_bounds__(256) k1_channelwise(
    const float* __restrict__ student, const float* __restrict__ teacher)
{
    const int b = blockIdx.y;
    const int p = blockIdx.x * 256 + threadIdx.x;
    const size_t base = (size_t)b * CHW + p;

    float Z = 0.f, S = 0.f, Tt = 0.f, Zs = 0.f;
    float t0, mx = -1e30f;

#pragma unroll
    for (int c = 0; c < CC; c++) {
        float tv = __ldg(teacher + base + (size_t)c * HW) * 0.25f;
        float sv = __ldg(student + base + (size_t)c * HW) * 0.25f;
        float e = __expf(tv);
        Z += e;
        S = fmaf(e, tv, S);
        Tt = fmaf(e, sv, Tt);
        Zs += __expf(sv);
        if (c == 0) t0 = tv;
        else        mx = fmaxf(mx, tv);
    }

    const float lZ = __logf(Z);
    const float ent = lZ - S / Z;
    const float kl = (S - Tt) / Z - lZ + __logf(Zs);

    const int idx = b * HW + p;
    g_ent[idx] = ent;
    g_kl[idx] = kl;
    g_fg[idx] = (mx > t0) ? 1 : 0;   // argmax != 0 (ties -> class 0)

    float entm = ent;
#pragma unroll
    for (int o = 16; o > 0; o >>= 1)
        entm = fmaxf(entm, __shfl_xor_sync(0xFFFFFFFF, entm, o));
    __shared__ float smax[8];
    if ((threadIdx.x & 31) == 0) smax[threadIdx.x >> 5] = entm;
    __syncthreads();
    if (threadIdx.x == 0) {
        float m = smax[0];
#pragma unroll
        for (int w = 1; w < 8; w++) m = fmaxf(m, smax[w]);
        atomicMax(&g_entmax[b], __float_as_int(m));
    }
}

// ---------------------------------------------------------------------------
// K2: bounded EDT + weights + finalize. Latency-optimized:
//  - ent/kl prefetched as float4 at kernel entry (overlaps all smem work)
//  - fg halo loaded as aligned u32 words (14/row), not bytes
//  - vertical pass: byte-SIMD (__vminu4), 14 words/row
//  - horizontal pass: byte-SIMD via __byte_perm + __vaddus4 + __vminu4,
//    4 pixels per thread computed simultaneously
// smem col layout: column cc maps to global col j0-12+cc (cc in [0,56));
// pixel tile col tx maps to cc = tx+12; halo taps for tx span cc=[tx+2, tx+22].
// ---------------------------------------------------------------------------
__global__ void __launch_bounds__(256) k2_edt_weights(float* __restrict__ out)
{
    const int b  = blockIdx.y;
    const int i0 = (blockIdx.x >> 3) * TS;
    const int j0 = (blockIdx.x & 7) * TS;
    const int tid = threadIdx.x;
    const int ty  = tid >> 3;          // tile row 0..31
    const int tx0 = (tid & 7) * 4;     // tile col base (4 consecutive px)

    // ---- prefetch ent/kl (coalesced float4) — starts DRAM latency early ----
    const int pidx = b * HW + (i0 + ty) * WW + j0 + tx0;
    const float4 ent4 = *(const float4*)(g_ent + pidx);
    const float4 kl4  = *(const float4*)(g_kl + pidx);

    __shared__ unsigned char sfg[EW][56];   // fg halo, word-aligned layout
    __shared__ unsigned char svv[TS][56];   // vertical min-d^2

    // ---- fg halo: 52 rows x 14 aligned u32 words ----
    for (int t = tid; t < EW * 14; t += 256) {
        int r = t / 14, k = t - r * 14;
        int gi = i0 - RAD + r;
        int g0 = j0 - 12 + 4 * k;       // j0 % 32 == 0 -> g0 % 4 == 0
        unsigned int word = 0;
        if (gi >= 0 && gi < HH) {
            const unsigned char* rowp = g_fg + b * HW + gi * WW;
            if (g0 >= 0 && g0 + 3 < WW) {
                word = *(const unsigned int*)(rowp + g0);
            } else {
#pragma unroll
                for (int bb = 0; bb < 4; bb++) {
                    int gj = g0 + bb;
                    if (gj >= 0 && gj < WW)
                        word |= (unsigned int)rowp[gj] << (8 * bb);
                }
            }
        }
        *(unsigned int*)&sfg[r][4 * k] = word;
    }
    __syncthreads();

    // ---- vertical 21-tap min, byte SIMD: term = 200 - fg*(200-d^2) ----
    for (int t = tid; t < TS * 14; t += 256) {
        int r = t / 14, wc = (t - r * 14) * 4;
        unsigned int v4 = 0xC8C8C8C8u;
#pragma unroll
        for (int dr = 0; dr < 21; dr++) {
            unsigned int f4 = *(const unsigned int*)&sfg[r + dr][wc];
            int d = dr - RAD;
            v4 = __vminu4(v4, 0xC8C8C8C8u - f4 * (unsigned int)(200 - d * d));
        }
        *(unsigned int*)&svv[r][wc] = v4;
    }
    __syncthreads();

    // ---- horizontal 21-tap min for 4 pixels at once ----
    // b[0..27] = svv[ty][tx0 .. tx0+27]; pixel l, shift s: tap byte index l+s+2
    unsigned int w[7];
#pragma unroll
    for (int k = 0; k < 7; k++)
        w[k] = *(const unsigned int*)&svv[ty][tx0 + 4 * k];

    unsigned int m4 = 0xC8C8C8C8u;
#pragma unroll
    for (int s = 0; s < 21; s++) {
        const int o = s + 2;
        const unsigned int sel = 0x3210u + 0x1111u * (o & 3);
        unsigned int V = __byte_perm(w[o >> 2], w[(o >> 2) + 1], sel);
        const int dd = s - RAD;
        const unsigned int C = (unsigned int)(dd * dd) * 0x01010101u;
        m4 = __vminu4(m4, __vaddus4(V, C));   // saturation only above threshold
    }

    // ---- weights ----
    const float Hm = __int_as_float(g_entmax[b]);
    const float invHm = 1.0f / (Hm + 1e-8f);
    const float entv[4] = {ent4.x, ent4.y, ent4.z, ent4.w};
    const float klv[4]  = {kl4.x,  kl4.y,  kl4.z,  kl4.w};

    float a_wkl = 0.f, a_w = 0.f;
#pragma unroll
    for (int l = 0; l < 4; l++) {
        const int d2 = (m4 >> (8 * l)) & 0xFF;
        if (d2 <= RAD * RAD) {
            const int tx = tx0 + l;
            float wd = __expf((float)d2 * (-1.0f / 50.0f));  // 2*sigma^2 = 50
            float bnd = 0.f;
            if (sfg[ty + RAD][tx + 12]) {
                bool er = sfg[ty + RAD - 1][tx + 12] && sfg[ty + RAD + 1][tx + 12]
                       && sfg[ty + RAD][tx + 11] && sfg[ty + RAD][tx + 13];
                if (!er) bnd = 1.f;
            }
            float conf = 0.1f + 0.9f * (1.f - entv[l] * invHm);
            float wgt = wd * (1.f + bnd) * conf;
            a_wkl = fmaf(wgt, klv[l], a_wkl);
            a_w  += wgt;
        }
    }

    // ---- reduce + finalize ----
#pragma unroll
    for (int o = 16; o > 0; o >>= 1) {
        a_wkl += __shfl_xor_sync(0xFFFFFFFF, a_wkl, o);
        a_w   += __shfl_xor_sync(0xFFFFFFFF, a_w, o);
    }
    __shared__ float r1[8], r2[8];
    if ((tid & 31) == 0) { r1[tid >> 5] = a_wkl; r2[tid >> 5] = a_w; }
    __syncthreads();

    if (tid == 0) {
        float s1 = 0.f, s2 = 0.f;
#pragma unroll
        for (int ww = 0; ww < 8; ww++) { s1 += r1[ww]; s2 += r2[ww]; }
        atomicAdd(&g_sum_wkl, (double)s1);
        atomicAdd(&g_sum_w, (double)s2);
        __threadfence();
        unsigned int t = atomicAdd(&g_done, 1u);
        if (t == NBLK2 - 1) {   // last block: finalize + reset for next replay
            double swkl = atomicAdd(&g_sum_wkl, 0.0);
            double sw   = atomicAdd(&g_sum_w, 0.0);
            out[0] = (float)(16.0 * swkl / (sw + 1e-8));
            g_sum_wkl = 0.0;
            g_sum_w = 0.0;
#pragma unroll
            for (int bb = 0; bb < BB; bb++) g_entmax[bb] = 0;
            atomicExch(&g_done, 0u);
        }
    }
}

extern "C" void kernel_launch(void* const* d_in, const int* in_sizes, int n_in,
                              void* d_out, int out_size)
{
    const float* student = (const float*)d_in[0];
    const float* teacher = (const float*)d_in[1];
    float* out = (float*)d_out;

    k1_channelwise<<<dim3(HW / 256, BB), 256>>>(student, teacher);
    k2_edt_weights<<<dim3(64, BB), 256>>>(out);
}